// round 1
// baseline (speedup 1.0000x reference)
#include <cuda_runtime.h>
#include <math.h>

// ---------------- problem constants ----------------
#define BATCH   32
#define IMGHW   56
#define CH      192
#define HEADS   6
#define HDIM    32
#define WSZ     7
#define NTOK    49          // WSZ*WSZ
#define NWIN    64          // (56/7)^2
#define BW      (BATCH*NWIN)    // 2048 windows
#define MROWS   (BW*NTOK)       // 100352 tokens
#define MLPH    768

// ---------------- scratch (device globals; no allocation allowed) ----------------
__device__ float g_q[BW*HEADS*NTOK*HDIM];
__device__ float g_k[BW*HEADS*NTOK*HDIM];
__device__ float g_v[BW*HEADS*NTOK*HDIM];
__device__ float g_attnout[MROWS*CH];
__device__ float g_x1[MROWS*CH];
__device__ float g_hidden[MROWS*MLPH];
__device__ float g_rpb[HEADS*NTOK*NTOK];

// Map a windowed-token row index -> pixel float-offset in the (B,56,56,192) image.
// Forward gather (roll -3 then window) and reverse scatter (window-reverse then
// roll +3) are the same mapping, so this serves input gather, shortcut read and
// x1 write alike.
__device__ __forceinline__ int row_to_pix(int m){
    int b_ = m / NTOK;
    int nn = m - b_*NTOK;
    int b  = b_ >> 6;
    int w  = b_ & 63;
    int wh = w >> 3, ww = w & 7;
    int r  = nn / 7, c = nn - r*7;
    int h  = wh*7 + r + 3; if (h >= IMGHW) h -= IMGHW;
    int x  = ww*7 + c + 3; if (x >= IMGHW) x -= IMGHW;
    return ((b*IMGHW + h)*IMGHW + x)*CH;
}

// ---------------- kernel 0: CPB MLP -> relative position bias table ----------------
__global__ __launch_bounds__(256)
void cpb_kernel(const float* __restrict__ w1, const float* __restrict__ b1,
                const float* __restrict__ w2){
    __shared__ float tbl[169*HEADS];
    const int tid = threadIdx.x;
    if (tid < 169){
        int dh = tid / 13, dw = tid - 13*(tid/13);
        float th = (float)(dh - 6) / 6.0f * 7.0f;
        float tw = (float)(dw - 6) / 6.0f * 7.0f;
        float sh = (th > 0.f) ? 1.f : ((th < 0.f) ? -1.f : 0.f);
        float sw = (tw > 0.f) ? 1.f : ((tw < 0.f) ? -1.f : 0.f);
        const float inv_log2_7 = 1.0f / log2f(7.0f);
        th = sh * log2f(fabsf(th) + 1.0f) * inv_log2_7;
        tw = sw * log2f(fabsf(tw) + 1.0f) * inv_log2_7;
        float acc[HEADS];
        #pragma unroll
        for (int h = 0; h < HEADS; h++) acc[h] = 0.f;
        for (int j = 0; j < 512; j++){
            float hv = w1[j*2]*th + w1[j*2+1]*tw + b1[j];
            hv = (hv > 0.f) ? hv : 0.01f*hv;   // leaky_relu 0.01
            #pragma unroll
            for (int h = 0; h < HEADS; h++) acc[h] += w2[h*512 + j] * hv;
        }
        #pragma unroll
        for (int h = 0; h < HEADS; h++) tbl[tid*HEADS + h] = acc[h];
    }
    __syncthreads();
    for (int p = tid; p < HEADS*NTOK*NTOK; p += 256){
        int h   = p / (NTOK*NTOK);
        int rem = p - h*(NTOK*NTOK);
        int i   = rem / NTOK, j = rem - i*NTOK;
        int dh  = i/7 - j/7 + 6;
        int dw  = (i - 7*(i/7)) - (j - 7*(j/7)) + 6;
        float v = tbl[(dh*13 + dw)*HEADS + h];
        g_rpb[p] = 14.0f / (1.0f + expf(-v));
    }
}

// ---------------- kernel 1: QKV GEMM (gathered A) ----------------
// M=100352, K=192, N=576. Tile 64x64, BK=16, 256 thr, 4x4 microtile.
__global__ __launch_bounds__(256)
void qkv_kernel(const float* __restrict__ x, const float* __restrict__ w,
                const float* __restrict__ bias){
    __shared__ __align__(16) float As[16][68];
    __shared__ __align__(16) float Bs[16][68];
    __shared__ int rpix[64];
    __shared__ int rq[64];
    const int tid = threadIdx.x;
    const int m0  = blockIdx.x * 64;
    const int n0  = blockIdx.y * 64;
    if (tid < 64){
        int m = m0 + tid;
        rpix[tid] = row_to_pix(m);
        int b_ = m / NTOK; int nn = m - b_*NTOK;
        rq[tid] = b_*(HEADS*NTOK*HDIM) + nn*HDIM;
    }
    const int ty = tid >> 4, tx = tid & 15;
    const int arow = tid >> 2, ak = (tid & 3) * 4;
    float acc[4][4];
    #pragma unroll
    for (int i=0;i<4;i++)
        #pragma unroll
        for (int j=0;j<4;j++) acc[i][j]=0.f;
    __syncthreads();
    for (int kt = 0; kt < 12; kt++){
        float4 av = *(const float4*)(x + rpix[arow] + kt*16 + ak);
        As[ak+0][arow]=av.x; As[ak+1][arow]=av.y; As[ak+2][arow]=av.z; As[ak+3][arow]=av.w;
        float4 bv = *(const float4*)(w + (n0 + arow)*CH + kt*16 + ak);
        Bs[ak+0][arow]=bv.x; Bs[ak+1][arow]=bv.y; Bs[ak+2][arow]=bv.z; Bs[ak+3][arow]=bv.w;
        __syncthreads();
        #pragma unroll
        for (int k = 0; k < 16; k++){
            float4 a = *(const float4*)&As[k][ty*4];
            float4 b = *(const float4*)&Bs[k][tx*4];
            float af[4] = {a.x,a.y,a.z,a.w};
            float bf[4] = {b.x,b.y,b.z,b.w};
            #pragma unroll
            for (int i=0;i<4;i++)
                #pragma unroll
                for (int j=0;j<4;j++) acc[i][j] += af[i]*bf[j];
        }
        __syncthreads();
    }
    const int col0 = n0 + tx*4;
    const int slot = col0 / 192;
    const int rem  = col0 - slot*192;
    const int head = rem >> 5;
    const int dd   = rem & 31;
    float* dst = (slot == 0) ? g_q : ((slot == 1) ? g_k : g_v);
    float4 bv = *(const float4*)(bias + col0);
    #pragma unroll
    for (int i = 0; i < 4; i++){
        int row = ty*4 + i;
        float4 o;
        o.x = acc[i][0] + bv.x; o.y = acc[i][1] + bv.y;
        o.z = acc[i][2] + bv.z; o.w = acc[i][3] + bv.w;
        *(float4*)(dst + rq[row] + head*(NTOK*HDIM) + dd) = o;
    }
}

// ---------------- kernel 2: windowed attention (one block per window,head) ----------------
__global__ __launch_bounds__(256)
void attn_kernel(const float* __restrict__ logit_scale){
    __shared__ __align__(16) float qT[32*52];    // [d][i], padded
    __shared__ __align__(16) float kT[32*52];
    __shared__ __align__(16) float vS[NTOK*HDIM];
    __shared__ float S[NTOK*NTOK];
    __shared__ __align__(16) float PT[NTOK*52];  // softmax result transposed [j][i]
    __shared__ int lab[NTOK];
    const int b_   = blockIdx.x;
    const int head = blockIdx.y;
    const int tid  = threadIdx.x;
    const float* qg = g_q + (b_*HEADS + head)*NTOK*HDIM;
    const float* kg = g_k + (b_*HEADS + head)*NTOK*HDIM;
    const float* vg = g_v + (b_*HEADS + head)*NTOK*HDIM;

    for (int idx = tid; idx < 32*52; idx += 256){ qT[idx]=0.f; kT[idx]=0.f; }
    for (int idx = tid; idx < NTOK*52; idx += 256){ PT[idx]=0.f; }
    __syncthreads();
    for (int idx = tid; idx < NTOK*HDIM; idx += 256){
        int n = idx >> 5, d = idx & 31;
        qT[d*52 + n] = qg[idx];
        kT[d*52 + n] = kg[idx];
        vS[idx]      = vg[idx];
    }
    if (tid < NTOK){
        int w  = b_ & 63;
        int wh = w >> 3, ww = w & 7;
        int r  = tid / 7, c = tid - 7*r;
        int hp = wh*7 + r, wp = ww*7 + c;
        int rb = (hp < 49) ? 0 : ((hp < 53) ? 1 : 2);
        int cb = (wp < 49) ? 0 : ((wp < 53) ? 1 : 2);
        lab[tid] = rb*3 + cb;
    }
    __syncthreads();
    // cosine-attention row normalization of q and k
    if (tid < 2*NTOK){
        int i = (tid < NTOK) ? tid : tid - NTOK;
        float* base = (tid < NTOK) ? qT : kT;
        float ss = 0.f;
        #pragma unroll
        for (int d = 0; d < 32; d++){ float t = base[d*52 + i]; ss += t*t; }
        float inv = 1.0f / fmaxf(sqrtf(ss), 1e-12f);
        #pragma unroll
        for (int d = 0; d < 32; d++) base[d*52 + i] *= inv;
    }
    __syncthreads();
    // S = qn @ kn^T * scale + rpb + mask   (4x4 microtiles, 13x13 grid)
    const float sc = expf(fminf(logit_scale[head], 4.60517019f));
    if (tid < 169){
        int bi = tid / 13, bj = tid - 13*bi;
        int i0 = bi*4, j0 = bj*4;
        float acc[4][4];
        #pragma unroll
        for (int a=0;a<4;a++)
            #pragma unroll
            for (int b=0;b<4;b++) acc[a][b]=0.f;
        #pragma unroll
        for (int d = 0; d < 32; d++){
            float4 qv = *(const float4*)&qT[d*52 + i0];
            float4 kv = *(const float4*)&kT[d*52 + j0];
            float qa[4] = {qv.x,qv.y,qv.z,qv.w};
            float ka[4] = {kv.x,kv.y,kv.z,kv.w};
            #pragma unroll
            for (int a=0;a<4;a++)
                #pragma unroll
                for (int b=0;b<4;b++) acc[a][b] += qa[a]*ka[b];
        }
        const float* rpb = g_rpb + head*NTOK*NTOK;
        #pragma unroll
        for (int a=0;a<4;a++){
            int i = i0 + a;
            if (i < NTOK){
                #pragma unroll
                for (int b=0;b<4;b++){
                    int j = j0 + b;
                    if (j < NTOK){
                        float mval = (lab[i] == lab[j]) ? 0.f : -100.f;
                        S[i*NTOK + j] = acc[a][b]*sc + rpb[i*NTOK + j] + mval;
                    }
                }
            }
        }
    }
    __syncthreads();
    // softmax rows -> PT transposed
    if (tid < NTOK){
        int i = tid;
        float mx = -1e30f;
        for (int j = 0; j < NTOK; j++) mx = fmaxf(mx, S[i*NTOK + j]);
        float sum = 0.f;
        for (int j = 0; j < NTOK; j++){
            float e = expf(S[i*NTOK + j] - mx);
            PT[j*52 + i] = e;
            sum += e;
        }
        float inv = 1.0f / sum;
        for (int j = 0; j < NTOK; j++) PT[j*52 + i] *= inv;
    }
    __syncthreads();
    // O = P @ V  (4x4 microtiles over 13 i-tiles x 8 d-tiles)
    if (tid < 104){
        int bi = tid >> 3, bd = tid & 7;
        int i0 = bi*4, d0 = bd*4;
        float acc[4][4];
        #pragma unroll
        for (int a=0;a<4;a++)
            #pragma unroll
            for (int b=0;b<4;b++) acc[a][b]=0.f;
        for (int j = 0; j < NTOK; j++){
            float4 pv = *(const float4*)&PT[j*52 + i0];
            float4 vv = *(const float4*)&vS[j*HDIM + d0];
            float pa[4] = {pv.x,pv.y,pv.z,pv.w};
            float va[4] = {vv.x,vv.y,vv.z,vv.w};
            #pragma unroll
            for (int a=0;a<4;a++)
                #pragma unroll
                for (int b=0;b<4;b++) acc[a][b] += pa[a]*va[b];
        }
        float* outb = g_attnout + (b_*NTOK)*CH + head*HDIM;
        #pragma unroll
        for (int a=0;a<4;a++){
            int i = i0 + a;
            if (i < NTOK){
                float4 o = {acc[a][0], acc[a][1], acc[a][2], acc[a][3]};
                *(float4*)(outb + i*CH + d0) = o;
            }
        }
    }
}

// ---------------- kernel 3: proj GEMM + window-reverse + LN1 + residual -> x1 ----------------
// Tile 64 rows x full 192 cols, BK=16. threads (8 x 32): each thread 8 rows x 6 cols (stride-32).
__global__ __launch_bounds__(256)
void proj_ln_kernel(const float* __restrict__ x, const float* __restrict__ w,
                    const float* __restrict__ bias, const float* __restrict__ nw,
                    const float* __restrict__ nb){
    __shared__ __align__(16) float As[16][68];
    __shared__ float Bs[16][196];
    __shared__ int rpix[64];
    const int tid = threadIdx.x;
    const int m0  = blockIdx.x * 64;
    if (tid < 64) rpix[tid] = row_to_pix(m0 + tid);
    const int ty = tid >> 5, lane = tid & 31;
    const int arow = tid >> 2, ak = (tid & 3) * 4;
    float acc[8][6];
    #pragma unroll
    for (int i=0;i<8;i++)
        #pragma unroll
        for (int j=0;j<6;j++) acc[i][j]=0.f;
    __syncthreads();
    for (int kt = 0; kt < 12; kt++){
        float4 av = *(const float4*)(g_attnout + (m0 + arow)*CH + kt*16 + ak);
        As[ak+0][arow]=av.x; As[ak+1][arow]=av.y; As[ak+2][arow]=av.z; As[ak+3][arow]=av.w;
        for (int t = tid; t < 768; t += 256){
            int bn = t >> 2, bk = (t & 3)*4;
            float4 bv = *(const float4*)(w + bn*CH + kt*16 + bk);
            Bs[bk+0][bn]=bv.x; Bs[bk+1][bn]=bv.y; Bs[bk+2][bn]=bv.z; Bs[bk+3][bn]=bv.w;
        }
        __syncthreads();
        #pragma unroll
        for (int k = 0; k < 16; k++){
            float4 a0 = *(const float4*)&As[k][ty*8];
            float4 a1 = *(const float4*)&As[k][ty*8+4];
            float ar[8] = {a0.x,a0.y,a0.z,a0.w,a1.x,a1.y,a1.z,a1.w};
            #pragma unroll
            for (int jj = 0; jj < 6; jj++){
                float bv = Bs[k][lane + 32*jj];
                #pragma unroll
                for (int i = 0; i < 8; i++) acc[i][jj] += ar[i]*bv;
            }
        }
        __syncthreads();
    }
    float bb[6], wl[6], bl[6];
    #pragma unroll
    for (int jj = 0; jj < 6; jj++){
        int col = lane + 32*jj;
        bb[jj] = bias[col]; wl[jj] = nw[col]; bl[jj] = nb[col];
    }
    const float invC = 1.0f / 192.0f;
    #pragma unroll
    for (int i = 0; i < 8; i++){
        int row = ty*8 + i;
        int pix = rpix[row];
        float y[6]; float s = 0.f;
        #pragma unroll
        for (int jj = 0; jj < 6; jj++){ y[jj] = acc[i][jj] + bb[jj]; s += y[jj]; }
        #pragma unroll
        for (int off = 16; off > 0; off >>= 1) s += __shfl_xor_sync(0xffffffffu, s, off);
        float mean = s * invC;
        float v = 0.f;
        #pragma unroll
        for (int jj = 0; jj < 6; jj++){ float d = y[jj]-mean; v += d*d; }
        #pragma unroll
        for (int off = 16; off > 0; off >>= 1) v += __shfl_xor_sync(0xffffffffu, v, off);
        float rstd = rsqrtf(v * invC + 1e-5f);
        #pragma unroll
        for (int jj = 0; jj < 6; jj++){
            int col = lane + 32*jj;
            g_x1[pix + col] = x[pix + col] + (y[jj]-mean)*rstd*wl[jj] + bl[jj];
        }
    }
}

// ---------------- kernel 4: fc1 GEMM + exact GELU -> hidden ----------------
__global__ __launch_bounds__(256)
void fc1_kernel(const float* __restrict__ w, const float* __restrict__ bias){
    __shared__ __align__(16) float As[16][68];
    __shared__ __align__(16) float Bs[16][68];
    const int tid = threadIdx.x;
    const int m0  = blockIdx.x * 64;
    const int n0  = blockIdx.y * 64;
    const int ty = tid >> 4, tx = tid & 15;
    const int arow = tid >> 2, ak = (tid & 3) * 4;
    float acc[4][4];
    #pragma unroll
    for (int i=0;i<4;i++)
        #pragma unroll
        for (int j=0;j<4;j++) acc[i][j]=0.f;
    for (int kt = 0; kt < 12; kt++){
        float4 av = *(const float4*)(g_x1 + (m0 + arow)*CH + kt*16 + ak);
        As[ak+0][arow]=av.x; As[ak+1][arow]=av.y; As[ak+2][arow]=av.z; As[ak+3][arow]=av.w;
        float4 bv = *(const float4*)(w + (n0 + arow)*CH + kt*16 + ak);
        Bs[ak+0][arow]=bv.x; Bs[ak+1][arow]=bv.y; Bs[ak+2][arow]=bv.z; Bs[ak+3][arow]=bv.w;
        __syncthreads();
        #pragma unroll
        for (int k = 0; k < 16; k++){
            float4 a = *(const float4*)&As[k][ty*4];
            float4 b = *(const float4*)&Bs[k][tx*4];
            float af[4] = {a.x,a.y,a.z,a.w};
            float bf[4] = {b.x,b.y,b.z,b.w};
            #pragma unroll
            for (int i=0;i<4;i++)
                #pragma unroll
                for (int j=0;j<4;j++) acc[i][j] += af[i]*bf[j];
        }
        __syncthreads();
    }
    const int col0 = n0 + tx*4;
    float4 bv = *(const float4*)(bias + col0);
    float bf[4] = {bv.x,bv.y,bv.z,bv.w};
    #pragma unroll
    for (int i = 0; i < 4; i++){
        int row = m0 + ty*4 + i;
        float4 o;
        float vv[4];
        #pragma unroll
        for (int j = 0; j < 4; j++){
            float t = acc[i][j] + bf[j];
            vv[j] = t * 0.5f * (1.0f + erff(t * 0.70710678118654752f));
        }
        o.x = vv[0]; o.y = vv[1]; o.z = vv[2]; o.w = vv[3];
        *(float4*)(g_hidden + row*MLPH + col0) = o;
    }
}

// ---------------- kernel 5: fc2 GEMM + LN2 + residual -> out ----------------
__global__ __launch_bounds__(256)
void fc2_ln_kernel(const float* __restrict__ w, const float* __restrict__ bias,
                   const float* __restrict__ nw, const float* __restrict__ nb,
                   float* __restrict__ out){
    __shared__ __align__(16) float As[16][68];
    __shared__ float Bs[16][196];
    const int tid = threadIdx.x;
    const int m0  = blockIdx.x * 64;
    const int ty = tid >> 5, lane = tid & 31;
    const int arow = tid >> 2, ak = (tid & 3) * 4;
    float acc[8][6];
    #pragma unroll
    for (int i=0;i<8;i++)
        #pragma unroll
        for (int j=0;j<6;j++) acc[i][j]=0.f;
    for (int kt = 0; kt < 48; kt++){
        float4 av = *(const float4*)(g_hidden + (m0 + arow)*MLPH + kt*16 + ak);
        As[ak+0][arow]=av.x; As[ak+1][arow]=av.y; As[ak+2][arow]=av.z; As[ak+3][arow]=av.w;
        for (int t = tid; t < 768; t += 256){
            int bn = t >> 2, bk = (t & 3)*4;
            float4 bv = *(const float4*)(w + bn*MLPH + kt*16 + bk);
            Bs[bk+0][bn]=bv.x; Bs[bk+1][bn]=bv.y; Bs[bk+2][bn]=bv.z; Bs[bk+3][bn]=bv.w;
        }
        __syncthreads();
        #pragma unroll
        for (int k = 0; k < 16; k++){
            float4 a0 = *(const float4*)&As[k][ty*8];
            float4 a1 = *(const float4*)&As[k][ty*8+4];
            float ar[8] = {a0.x,a0.y,a0.z,a0.w,a1.x,a1.y,a1.z,a1.w};
            #pragma unroll
            for (int jj = 0; jj < 6; jj++){
                float bv = Bs[k][lane + 32*jj];
                #pragma unroll
                for (int i = 0; i < 8; i++) acc[i][jj] += ar[i]*bv;
            }
        }
        __syncthreads();
    }
    float bb[6], wl[6], bl[6];
    #pragma unroll
    for (int jj = 0; jj < 6; jj++){
        int col = lane + 32*jj;
        bb[jj] = bias[col]; wl[jj] = nw[col]; bl[jj] = nb[col];
    }
    const float invC = 1.0f / 192.0f;
    #pragma unroll
    for (int i = 0; i < 8; i++){
        int row = m0 + ty*8 + i;
        float y[6]; float s = 0.f;
        #pragma unroll
        for (int jj = 0; jj < 6; jj++){ y[jj] = acc[i][jj] + bb[jj]; s += y[jj]; }
        #pragma unroll
        for (int off = 16; off > 0; off >>= 1) s += __shfl_xor_sync(0xffffffffu, s, off);
        float mean = s * invC;
        float v = 0.f;
        #pragma unroll
        for (int jj = 0; jj < 6; jj++){ float d = y[jj]-mean; v += d*d; }
        #pragma unroll
        for (int off = 16; off > 0; off >>= 1) v += __shfl_xor_sync(0xffffffffu, v, off);
        float rstd = rsqrtf(v * invC + 1e-5f);
        #pragma unroll
        for (int jj = 0; jj < 6; jj++){
            int col = lane + 32*jj;
            out[row*CH + col] = g_x1[row*CH + col] + (y[jj]-mean)*rstd*wl[jj] + bl[jj];
        }
    }
}

// ---------------- launch ----------------
extern "C" void kernel_launch(void* const* d_in, const int* in_sizes, int n_in,
                              void* d_out, int out_size){
    const float* x        = (const float*)d_in[0];
    const float* qkv_w    = (const float*)d_in[1];
    const float* qkv_b    = (const float*)d_in[2];
    const float* proj_w   = (const float*)d_in[3];
    const float* proj_b   = (const float*)d_in[4];
    const float* lscale   = (const float*)d_in[5];
    const float* cpb_w1   = (const float*)d_in[6];
    const float* cpb_b1   = (const float*)d_in[7];
    const float* cpb_w2   = (const float*)d_in[8];
    const float* norm1_w  = (const float*)d_in[9];
    const float* norm1_b  = (const float*)d_in[10];
    const float* norm2_w  = (const float*)d_in[11];
    const float* norm2_b  = (const float*)d_in[12];
    const float* fc1_w    = (const float*)d_in[13];
    const float* fc1_b    = (const float*)d_in[14];
    const float* fc2_w    = (const float*)d_in[15];
    const float* fc2_b    = (const float*)d_in[16];
    float* out = (float*)d_out;

    cpb_kernel<<<1, 256>>>(cpb_w1, cpb_b1, cpb_w2);
    qkv_kernel<<<dim3(MROWS/64, 576/64), 256>>>(x, qkv_w, qkv_b);
    attn_kernel<<<dim3(BW, HEADS), 256>>>(lscale);
    proj_ln_kernel<<<MROWS/64, 256>>>(x, proj_w, proj_b, norm1_w, norm1_b);
    fc1_kernel<<<dim3(MROWS/64, MLPH/64), 256>>>(fc1_w, fc1_b);
    fc2_ln_kernel<<<MROWS/64, 256>>>(fc2_w, fc2_b, norm2_w, norm2_b, out);
}

// round 2
// speedup vs baseline: 1.6676x; 1.6676x over previous
#include <cuda_runtime.h>
#include <math.h>

// ---------------- problem constants ----------------
#define BATCH   32
#define IMGHW   56
#define CH      192
#define HEADS   6
#define HDIM    32
#define WSZ     7
#define NTOK    49
#define NWIN    64
#define BW      (BATCH*NWIN)     // 2048 windows
#define MROWS   (BW*NTOK)        // 100352 tokens
#define MLPH    768

// ---------------- scratch ----------------
__device__ float g_q[BW*HEADS*NTOK*HDIM];
__device__ float g_k[BW*HEADS*NTOK*HDIM];
__device__ float g_v[BW*HEADS*NTOK*HDIM];
__device__ float g_attnout[MROWS*CH];
__device__ float g_x1[MROWS*CH];
__device__ float g_hidden[MROWS*MLPH];
__device__ float g_rpb[HEADS*NTOK*NTOK];

__device__ __forceinline__ int row_to_pix(int m){
    int b_ = m / NTOK;
    int nn = m - b_*NTOK;
    int b  = b_ >> 6;
    int w  = b_ & 63;
    int wh = w >> 3, ww = w & 7;
    int r  = nn / 7, c = nn - r*7;
    int h  = wh*7 + r + 3; if (h >= IMGHW) h -= IMGHW;
    int x  = ww*7 + c + 3; if (x >= IMGHW) x -= IMGHW;
    return ((b*IMGHW + h)*IMGHW + x)*CH;
}

// ---------------- tf32 helpers ----------------
__device__ __forceinline__ unsigned tf32r(float x){
    unsigned u; asm("cvt.rna.tf32.f32 %0, %1;" : "=r"(u) : "f"(x)); return u;
}
__device__ __forceinline__ void mma8(float* c, const unsigned* a, const unsigned* b){
    asm volatile("mma.sync.aligned.m16n8k8.row.col.f32.tf32.tf32.f32 "
        "{%0,%1,%2,%3},{%4,%5,%6,%7},{%8,%9},{%0,%1,%2,%3};"
        : "+f"(c[0]), "+f"(c[1]), "+f"(c[2]), "+f"(c[3])
        : "r"(a[0]), "r"(a[1]), "r"(a[2]), "r"(a[3]), "r"(b[0]), "r"(b[1]));
}

// ---------------- kernel 0: CPB MLP -> bias table ----------------
__global__ __launch_bounds__(256)
void cpb_kernel(const float* __restrict__ w1, const float* __restrict__ b1,
                const float* __restrict__ w2){
    __shared__ float tbl[169*HEADS];
    const int tid = threadIdx.x;
    if (tid < 169){
        int dh = tid / 13, dw = tid - 13*(tid/13);
        float th = (float)(dh - 6) / 6.0f * 7.0f;
        float tw = (float)(dw - 6) / 6.0f * 7.0f;
        float sh = (th > 0.f) ? 1.f : ((th < 0.f) ? -1.f : 0.f);
        float sw = (tw > 0.f) ? 1.f : ((tw < 0.f) ? -1.f : 0.f);
        const float inv_log2_7 = 1.0f / log2f(7.0f);
        th = sh * log2f(fabsf(th) + 1.0f) * inv_log2_7;
        tw = sw * log2f(fabsf(tw) + 1.0f) * inv_log2_7;
        float acc[HEADS];
        #pragma unroll
        for (int h = 0; h < HEADS; h++) acc[h] = 0.f;
        for (int j = 0; j < 512; j++){
            float hv = w1[j*2]*th + w1[j*2+1]*tw + b1[j];
            hv = (hv > 0.f) ? hv : 0.01f*hv;
            #pragma unroll
            for (int h = 0; h < HEADS; h++) acc[h] += w2[h*512 + j] * hv;
        }
        #pragma unroll
        for (int h = 0; h < HEADS; h++) tbl[tid*HEADS + h] = acc[h];
    }
    __syncthreads();
    for (int p = tid; p < HEADS*NTOK*NTOK; p += 256){
        int h   = p / (NTOK*NTOK);
        int rem = p - h*(NTOK*NTOK);
        int i   = rem / NTOK, j = rem - i*NTOK;
        int dh  = i/7 - j/7 + 6;
        int dw  = (i - 7*(i/7)) - (j - 7*(j/7)) + 6;
        float v = tbl[(dh*13 + dw)*HEADS + h];
        g_rpb[p] = 14.0f / (1.0f + expf(-v));
    }
}

// ---------------- kernel 1: QKV GEMM, 3xTF32, gathered A ----------------
// M=100352(BM=128), N=576(BN=64), K=192(BK=16). 256 thr = 8 warps (4x2), warp 32x32.
__global__ __launch_bounds__(256)
void qkv_kernel(const float* __restrict__ x, const float* __restrict__ w,
                const float* __restrict__ bias){
    __shared__ unsigned AsH[128][20], AsL[128][20];
    __shared__ unsigned BsH[64][20],  BsL[64][20];
    __shared__ int rpix[128];
    __shared__ int rq[128];
    const int tid  = threadIdx.x;
    const int m0   = blockIdx.x * 128;
    const int n0   = blockIdx.y * 64;
    const int warp = tid >> 5, lane = tid & 31;
    const int g = lane >> 2, t = lane & 3;
    const int warp_m = warp & 3, warp_n = warp >> 2;
    const int m_w = warp_m*32, n_w = warp_n*32;
    if (tid < 128){
        int m = m0 + tid;
        rpix[tid] = row_to_pix(m);
        int b_ = m / NTOK; int nn = m - b_*NTOK;
        rq[tid] = b_*(HEADS*NTOK*HDIM) + nn*HDIM;
    }
    const int rowA = tid >> 1, ka = (tid & 1) * 8;
    const int rowB = tid >> 2, kb = (tid & 3) * 4;
    float c[2][4][4];
    #pragma unroll
    for (int i=0;i<2;i++) for (int j=0;j<4;j++) for (int q=0;q<4;q++) c[i][j][q]=0.f;
    __syncthreads();

    for (int kt = 0; kt < 12; kt++){
        float4 a0 = *(const float4*)(x + rpix[rowA] + kt*16 + ka);
        float4 a1 = *(const float4*)(x + rpix[rowA] + kt*16 + ka + 4);
        float4 bv = *(const float4*)(w + (n0 + rowB)*CH + kt*16 + kb);
        __syncthreads();
        {
            float av[8] = {a0.x,a0.y,a0.z,a0.w,a1.x,a1.y,a1.z,a1.w};
            #pragma unroll
            for (int q = 0; q < 8; q++){
                unsigned h = tf32r(av[q]);
                AsH[rowA][ka+q] = h;
                AsL[rowA][ka+q] = tf32r(av[q] - __uint_as_float(h));
            }
            float bf[4] = {bv.x,bv.y,bv.z,bv.w};
            #pragma unroll
            for (int q = 0; q < 4; q++){
                unsigned h = tf32r(bf[q]);
                BsH[rowB][kb+q] = h;
                BsL[rowB][kb+q] = tf32r(bf[q] - __uint_as_float(h));
            }
        }
        __syncthreads();
        #pragma unroll
        for (int ks = 0; ks < 2; ks++){
            const int k0 = ks*8;
            unsigned ah[2][4], al[2][4];
            #pragma unroll
            for (int mi = 0; mi < 2; mi++){
                int mr = m_w + mi*16;
                ah[mi][0] = AsH[mr+g][k0+t];     al[mi][0] = AsL[mr+g][k0+t];
                ah[mi][1] = AsH[mr+8+g][k0+t];   al[mi][1] = AsL[mr+8+g][k0+t];
                ah[mi][2] = AsH[mr+g][k0+t+4];   al[mi][2] = AsL[mr+g][k0+t+4];
                ah[mi][3] = AsH[mr+8+g][k0+t+4]; al[mi][3] = AsL[mr+8+g][k0+t+4];
            }
            unsigned bh[4][2], bl[4][2];
            #pragma unroll
            for (int ni = 0; ni < 4; ni++){
                int nr = n_w + ni*8 + g;
                bh[ni][0] = BsH[nr][k0+t];   bl[ni][0] = BsL[nr][k0+t];
                bh[ni][1] = BsH[nr][k0+t+4]; bl[ni][1] = BsL[nr][k0+t+4];
            }
            #pragma unroll
            for (int mi = 0; mi < 2; mi++)
                #pragma unroll
                for (int ni = 0; ni < 4; ni++){
                    mma8(c[mi][ni], al[mi], bh[ni]);
                    mma8(c[mi][ni], ah[mi], bl[ni]);
                    mma8(c[mi][ni], ah[mi], bh[ni]);
                }
        }
        __syncthreads();
    }
    #pragma unroll
    for (int mi = 0; mi < 2; mi++){
        #pragma unroll
        for (int ni = 0; ni < 4; ni++){
            int col  = n0 + n_w + ni*8 + t*2;
            int slot = col / 192;
            int rem  = col - slot*192;
            float* dst = (slot == 0) ? g_q : ((slot == 1) ? g_k : g_v);
            int off = (rem >> 5)*(NTOK*HDIM) + (rem & 31);
            float2 bv = *(const float2*)(bias + col);
            int r0 = m_w + mi*16 + g;
            float2 o0 = {c[mi][ni][0] + bv.x, c[mi][ni][1] + bv.y};
            *(float2*)(dst + rq[r0] + off) = o0;
            float2 o1 = {c[mi][ni][2] + bv.x, c[mi][ni][3] + bv.y};
            *(float2*)(dst + rq[r0+8] + off) = o1;
        }
    }
}

// ---------------- kernel 2: windowed attention ----------------
__global__ __launch_bounds__(256)
void attn_kernel(const float* __restrict__ logit_scale){
    __shared__ __align__(16) float qT[32*52];
    __shared__ __align__(16) float kT[32*52];
    __shared__ __align__(16) float vS[NTOK*HDIM];
    __shared__ float S[NTOK*NTOK];
    __shared__ __align__(16) float PT[NTOK*52];
    __shared__ int lab[NTOK];
    const int b_   = blockIdx.x;
    const int head = blockIdx.y;
    const int tid  = threadIdx.x;
    const float* qg = g_q + (b_*HEADS + head)*NTOK*HDIM;
    const float* kg = g_k + (b_*HEADS + head)*NTOK*HDIM;
    const float* vg = g_v + (b_*HEADS + head)*NTOK*HDIM;

    for (int idx = tid; idx < 32*52; idx += 256){ qT[idx]=0.f; kT[idx]=0.f; }
    for (int idx = tid; idx < NTOK*52; idx += 256){ PT[idx]=0.f; }
    __syncthreads();
    for (int idx = tid; idx < NTOK*HDIM; idx += 256){
        int n = idx >> 5, d = idx & 31;
        qT[d*52 + n] = qg[idx];
        kT[d*52 + n] = kg[idx];
        vS[idx]      = vg[idx];
    }
    if (tid < NTOK){
        int w  = b_ & 63;
        int wh = w >> 3, ww = w & 7;
        int r  = tid / 7, c = tid - 7*r;
        int hp = wh*7 + r, wp = ww*7 + c;
        int rb = (hp < 49) ? 0 : ((hp < 53) ? 1 : 2);
        int cb = (wp < 49) ? 0 : ((wp < 53) ? 1 : 2);
        lab[tid] = rb*3 + cb;
    }
    __syncthreads();
    if (tid < 2*NTOK){
        int i = (tid < NTOK) ? tid : tid - NTOK;
        float* base = (tid < NTOK) ? qT : kT;
        float ss = 0.f;
        #pragma unroll
        for (int d = 0; d < 32; d++){ float v = base[d*52 + i]; ss += v*v; }
        float inv = 1.0f / fmaxf(sqrtf(ss), 1e-12f);
        #pragma unroll
        for (int d = 0; d < 32; d++) base[d*52 + i] *= inv;
    }
    __syncthreads();
    const float sc = expf(fminf(logit_scale[head], 4.60517019f));
    if (tid < 169){
        int bi = tid / 13, bj = tid - 13*bi;
        int i0 = bi*4, j0 = bj*4;
        float acc[4][4];
        #pragma unroll
        for (int a=0;a<4;a++) for (int b=0;b<4;b++) acc[a][b]=0.f;
        #pragma unroll
        for (int d = 0; d < 32; d++){
            float4 qv = *(const float4*)&qT[d*52 + i0];
            float4 kv = *(const float4*)&kT[d*52 + j0];
            float qa[4] = {qv.x,qv.y,qv.z,qv.w};
            float kk[4] = {kv.x,kv.y,kv.z,kv.w};
            #pragma unroll
            for (int a=0;a<4;a++)
                #pragma unroll
                for (int b=0;b<4;b++) acc[a][b] += qa[a]*kk[b];
        }
        const float* rpb = g_rpb + head*NTOK*NTOK;
        #pragma unroll
        for (int a=0;a<4;a++){
            int i = i0 + a;
            if (i < NTOK){
                #pragma unroll
                for (int b=0;b<4;b++){
                    int j = j0 + b;
                    if (j < NTOK){
                        float mval = (lab[i] == lab[j]) ? 0.f : -100.f;
                        S[i*NTOK + j] = acc[a][b]*sc + rpb[i*NTOK + j] + mval;
                    }
                }
            }
        }
    }
    __syncthreads();
    if (tid < NTOK){
        int i = tid;
        float mx = -1e30f;
        for (int j = 0; j < NTOK; j++) mx = fmaxf(mx, S[i*NTOK + j]);
        float sum = 0.f;
        for (int j = 0; j < NTOK; j++){
            float e = expf(S[i*NTOK + j] - mx);
            PT[j*52 + i] = e;
            sum += e;
        }
        float inv = 1.0f / sum;
        for (int j = 0; j < NTOK; j++) PT[j*52 + i] *= inv;
    }
    __syncthreads();
    if (tid < 104){
        int bi = tid >> 3, bd = tid & 7;
        int i0 = bi*4, d0 = bd*4;
        float acc[4][4];
        #pragma unroll
        for (int a=0;a<4;a++) for (int b=0;b<4;b++) acc[a][b]=0.f;
        for (int j = 0; j < NTOK; j++){
            float4 pv = *(const float4*)&PT[j*52 + i0];
            float4 vv = *(const float4*)&vS[j*HDIM + d0];
            float pa[4] = {pv.x,pv.y,pv.z,pv.w};
            float va[4] = {vv.x,vv.y,vv.z,vv.w};
            #pragma unroll
            for (int a=0;a<4;a++)
                #pragma unroll
                for (int b=0;b<4;b++) acc[a][b] += pa[a]*va[b];
        }
        float* outb = g_attnout + (b_*NTOK)*CH + head*HDIM;
        #pragma unroll
        for (int a=0;a<4;a++){
            int i = i0 + a;
            if (i < NTOK){
                float4 o = {acc[a][0], acc[a][1], acc[a][2], acc[a][3]};
                *(float4*)(outb + i*CH + d0) = o;
            }
        }
    }
}

// ---------------- kernels 3/5: GEMM(BMx192) + LN + residual, TF32 ----------------
// BM=64, BN=192, BK=16. 8 warps (2x4), warp 32x48.
template<bool PIX>
__global__ __launch_bounds__(256)
void gemm_ln_kernel(const float* __restrict__ A, const float* __restrict__ w,
                    const float* __restrict__ bias, const float* __restrict__ nw,
                    const float* __restrict__ nb, const float* __restrict__ res,
                    float* __restrict__ out, int K){
    __shared__ unsigned As[64][20];
    __shared__ unsigned Bs[192][20];
    __shared__ float red_s[64][4], red_q[64][4];
    __shared__ int rpix[64];
    const int tid  = threadIdx.x;
    const int m0   = blockIdx.x * 64;
    const int warp = tid >> 5, lane = tid & 31;
    const int g = lane >> 2, t = lane & 3;
    const int warp_m = warp >> 2, warp_n = warp & 3;
    const int m_w = warp_m*32, n_w = warp_n*48;
    if (PIX && tid < 64) rpix[tid] = row_to_pix(m0 + tid);
    const int rowA = tid >> 2, ka = (tid & 3) * 4;
    float c[2][6][4];
    #pragma unroll
    for (int i=0;i<2;i++) for (int j=0;j<6;j++) for (int q=0;q<4;q++) c[i][j][q]=0.f;
    __syncthreads();

    const int KT = K >> 4;
    for (int kt = 0; kt < KT; kt++){
        float4 av  = *(const float4*)(A + (m0 + rowA)*K + kt*16 + ka);
        float4 bv0 = *(const float4*)(w + (rowA      )*K + kt*16 + ka);
        float4 bv1 = *(const float4*)(w + (rowA + 64 )*K + kt*16 + ka);
        float4 bv2 = *(const float4*)(w + (rowA + 128)*K + kt*16 + ka);
        __syncthreads();
        As[rowA][ka+0]=tf32r(av.x); As[rowA][ka+1]=tf32r(av.y);
        As[rowA][ka+2]=tf32r(av.z); As[rowA][ka+3]=tf32r(av.w);
        Bs[rowA][ka+0]=tf32r(bv0.x); Bs[rowA][ka+1]=tf32r(bv0.y);
        Bs[rowA][ka+2]=tf32r(bv0.z); Bs[rowA][ka+3]=tf32r(bv0.w);
        Bs[rowA+64][ka+0]=tf32r(bv1.x); Bs[rowA+64][ka+1]=tf32r(bv1.y);
        Bs[rowA+64][ka+2]=tf32r(bv1.z); Bs[rowA+64][ka+3]=tf32r(bv1.w);
        Bs[rowA+128][ka+0]=tf32r(bv2.x); Bs[rowA+128][ka+1]=tf32r(bv2.y);
        Bs[rowA+128][ka+2]=tf32r(bv2.z); Bs[rowA+128][ka+3]=tf32r(bv2.w);
        __syncthreads();
        #pragma unroll
        for (int ks = 0; ks < 2; ks++){
            const int k0 = ks*8;
            unsigned a[2][4];
            #pragma unroll
            for (int mi = 0; mi < 2; mi++){
                int mr = m_w + mi*16;
                a[mi][0] = As[mr+g][k0+t];
                a[mi][1] = As[mr+8+g][k0+t];
                a[mi][2] = As[mr+g][k0+t+4];
                a[mi][3] = As[mr+8+g][k0+t+4];
            }
            unsigned b[6][2];
            #pragma unroll
            for (int ni = 0; ni < 6; ni++){
                int nr = n_w + ni*8 + g;
                b[ni][0] = Bs[nr][k0+t];
                b[ni][1] = Bs[nr][k0+t+4];
            }
            #pragma unroll
            for (int mi = 0; mi < 2; mi++)
                #pragma unroll
                for (int ni = 0; ni < 6; ni++)
                    mma8(c[mi][ni], a[mi], b[ni]);
        }
        __syncthreads();
    }
    // bias add
    float2 bb[6];
    #pragma unroll
    for (int ni = 0; ni < 6; ni++){
        int col = n_w + ni*8 + t*2;
        bb[ni] = *(const float2*)(bias + col);
        #pragma unroll
        for (int mi = 0; mi < 2; mi++){
            c[mi][ni][0] += bb[ni].x; c[mi][ni][1] += bb[ni].y;
            c[mi][ni][2] += bb[ni].x; c[mi][ni][3] += bb[ni].y;
        }
    }
    // per-row partial sums over this warp's 48 cols
    #pragma unroll
    for (int mi = 0; mi < 2; mi++){
        float s0=0,q0=0,s1=0,q1=0;
        #pragma unroll
        for (int ni = 0; ni < 6; ni++){
            s0 += c[mi][ni][0] + c[mi][ni][1];
            q0 += c[mi][ni][0]*c[mi][ni][0] + c[mi][ni][1]*c[mi][ni][1];
            s1 += c[mi][ni][2] + c[mi][ni][3];
            q1 += c[mi][ni][2]*c[mi][ni][2] + c[mi][ni][3]*c[mi][ni][3];
        }
        #pragma unroll
        for (int off = 1; off <= 2; off <<= 1){
            s0 += __shfl_xor_sync(0xffffffffu, s0, off);
            q0 += __shfl_xor_sync(0xffffffffu, q0, off);
            s1 += __shfl_xor_sync(0xffffffffu, s1, off);
            q1 += __shfl_xor_sync(0xffffffffu, q1, off);
        }
        if (t == 0){
            int r0 = m_w + mi*16 + g;
            red_s[r0][warp_n] = s0; red_q[r0][warp_n] = q0;
            red_s[r0+8][warp_n] = s1; red_q[r0+8][warp_n] = q1;
        }
    }
    __syncthreads();
    const float invC = 1.0f / 192.0f;
    #pragma unroll
    for (int mi = 0; mi < 2; mi++){
        #pragma unroll
        for (int half = 0; half < 2; half++){
            int row = m_w + mi*16 + half*8 + g;
            float s = red_s[row][0] + red_s[row][1] + red_s[row][2] + red_s[row][3];
            float q = red_q[row][0] + red_q[row][1] + red_q[row][2] + red_q[row][3];
            float mean = s * invC;
            float var  = q * invC - mean*mean;
            float rstd = rsqrtf(var + 1e-5f);
            long gi = PIX ? (long)rpix[row] : (long)(m0 + row)*CH;
            #pragma unroll
            for (int ni = 0; ni < 6; ni++){
                int col = n_w + ni*8 + t*2;
                float y0 = c[mi][ni][half*2+0];
                float y1 = c[mi][ni][half*2+1];
                float2 rv = *(const float2*)(res + gi + col);
                float2 wv = *(const float2*)(nw + col);
                float2 bn = *(const float2*)(nb + col);
                float2 o;
                o.x = rv.x + (y0 - mean)*rstd*wv.x + bn.x;
                o.y = rv.y + (y1 - mean)*rstd*wv.y + bn.y;
                *(float2*)(out + gi + col) = o;
            }
        }
    }
}

// ---------------- kernel 4: fc1 GEMM + exact GELU, TF32 ----------------
// BM=128, BN=64, BK=16, K=192.
__global__ __launch_bounds__(256)
void fc1_kernel(const float* __restrict__ w, const float* __restrict__ bias){
    __shared__ unsigned As[128][20];
    __shared__ unsigned Bs[64][20];
    const int tid  = threadIdx.x;
    const int m0   = blockIdx.x * 128;
    const int n0   = blockIdx.y * 64;
    const int warp = tid >> 5, lane = tid & 31;
    const int g = lane >> 2, t = lane & 3;
    const int warp_m = warp & 3, warp_n = warp >> 2;
    const int m_w = warp_m*32, n_w = warp_n*32;
    const int rowA = tid >> 1, ka = (tid & 1) * 8;
    const int rowB = tid >> 2, kb = (tid & 3) * 4;
    float c[2][4][4];
    #pragma unroll
    for (int i=0;i<2;i++) for (int j=0;j<4;j++) for (int q=0;q<4;q++) c[i][j][q]=0.f;

    for (int kt = 0; kt < 12; kt++){
        float4 a0 = *(const float4*)(g_x1 + (m0 + rowA)*CH + kt*16 + ka);
        float4 a1 = *(const float4*)(g_x1 + (m0 + rowA)*CH + kt*16 + ka + 4);
        float4 bv = *(const float4*)(w + (n0 + rowB)*CH + kt*16 + kb);
        __syncthreads();
        As[rowA][ka+0]=tf32r(a0.x); As[rowA][ka+1]=tf32r(a0.y);
        As[rowA][ka+2]=tf32r(a0.z); As[rowA][ka+3]=tf32r(a0.w);
        As[rowA][ka+4]=tf32r(a1.x); As[rowA][ka+5]=tf32r(a1.y);
        As[rowA][ka+6]=tf32r(a1.z); As[rowA][ka+7]=tf32r(a1.w);
        Bs[rowB][kb+0]=tf32r(bv.x); Bs[rowB][kb+1]=tf32r(bv.y);
        Bs[rowB][kb+2]=tf32r(bv.z); Bs[rowB][kb+3]=tf32r(bv.w);
        __syncthreads();
        #pragma unroll
        for (int ks = 0; ks < 2; ks++){
            const int k0 = ks*8;
            unsigned a[2][4];
            #pragma unroll
            for (int mi = 0; mi < 2; mi++){
                int mr = m_w + mi*16;
                a[mi][0] = As[mr+g][k0+t];
                a[mi][1] = As[mr+8+g][k0+t];
                a[mi][2] = As[mr+g][k0+t+4];
                a[mi][3] = As[mr+8+g][k0+t+4];
            }
            unsigned b[4][2];
            #pragma unroll
            for (int ni = 0; ni < 4; ni++){
                int nr = n_w + ni*8 + g;
                b[ni][0] = Bs[nr][k0+t];
                b[ni][1] = Bs[nr][k0+t+4];
            }
            #pragma unroll
            for (int mi = 0; mi < 2; mi++)
                #pragma unroll
                for (int ni = 0; ni < 4; ni++)
                    mma8(c[mi][ni], a[mi], b[ni]);
        }
        __syncthreads();
    }
    #pragma unroll
    for (int mi = 0; mi < 2; mi++){
        #pragma unroll
        for (int ni = 0; ni < 4; ni++){
            int col = n0 + n_w + ni*8 + t*2;
            float2 bv = *(const float2*)(bias + col);
            int r0 = m0 + m_w + mi*16 + g;
            float v0 = c[mi][ni][0] + bv.x;
            float v1 = c[mi][ni][1] + bv.y;
            float v2 = c[mi][ni][2] + bv.x;
            float v3 = c[mi][ni][3] + bv.y;
            float2 o0, o1;
            o0.x = v0 * 0.5f * (1.0f + erff(v0 * 0.70710678118654752f));
            o0.y = v1 * 0.5f * (1.0f + erff(v1 * 0.70710678118654752f));
            o1.x = v2 * 0.5f * (1.0f + erff(v2 * 0.70710678118654752f));
            o1.y = v3 * 0.5f * (1.0f + erff(v3 * 0.70710678118654752f));
            *(float2*)(g_hidden + (long)r0*MLPH + col) = o0;
            *(float2*)(g_hidden + (long)(r0+8)*MLPH + col) = o1;
        }
    }
}

// ---------------- launch ----------------
extern "C" void kernel_launch(void* const* d_in, const int* in_sizes, int n_in,
                              void* d_out, int out_size){
    const float* x        = (const float*)d_in[0];
    const float* qkv_w    = (const float*)d_in[1];
    const float* qkv_b    = (const float*)d_in[2];
    const float* proj_w   = (const float*)d_in[3];
    const float* proj_b   = (const float*)d_in[4];
    const float* lscale   = (const float*)d_in[5];
    const float* cpb_w1   = (const float*)d_in[6];
    const float* cpb_b1   = (const float*)d_in[7];
    const float* cpb_w2   = (const float*)d_in[8];
    const float* norm1_w  = (const float*)d_in[9];
    const float* norm1_b  = (const float*)d_in[10];
    const float* norm2_w  = (const float*)d_in[11];
    const float* norm2_b  = (const float*)d_in[12];
    const float* fc1_w    = (const float*)d_in[13];
    const float* fc1_b    = (const float*)d_in[14];
    const float* fc2_w    = (const float*)d_in[15];
    const float* fc2_b    = (const float*)d_in[16];
    float* out = (float*)d_out;

    float* gq; cudaGetSymbolAddress((void**)&gq, g_q); // resolve at launch (no alloc)
    (void)gq;

    float *p_attnout, *p_x1, *p_hidden;
    cudaGetSymbolAddress((void**)&p_attnout, g_attnout);
    cudaGetSymbolAddress((void**)&p_x1, g_x1);
    cudaGetSymbolAddress((void**)&p_hidden, g_hidden);

    cpb_kernel<<<1, 256>>>(cpb_w1, cpb_b1, cpb_w2);
    qkv_kernel<<<dim3(MROWS/128, 576/64), 256>>>(x, qkv_w, qkv_b);
    attn_kernel<<<dim3(BW, HEADS), 256>>>(lscale);
    // proj: A=g_attnout, residual=x (pix), out=g_x1 (pix)
    gemm_ln_kernel<true><<<MROWS/64, 256>>>(p_attnout, proj_w, proj_b,
                                            norm1_w, norm1_b, x, p_x1, CH);
    fc1_kernel<<<dim3(MROWS/128, MLPH/64), 256>>>(fc1_w, fc1_b);
    // fc2: A=g_hidden, residual=g_x1 (linear), out=d_out (linear)
    gemm_ln_kernel<false><<<MROWS/64, 256>>>(p_hidden, fc2_w, fc2_b,
                                             norm2_w, norm2_b, p_x1, out, MLPH);
}

// round 4
// speedup vs baseline: 1.9431x; 1.1652x over previous
#include <cuda_runtime.h>
#include <math.h>

// ---------------- problem constants ----------------
#define BATCH   32
#define IMGHW   56
#define CH      192
#define HEADS   6
#define HDIM    32
#define WSZ     7
#define NTOK    49
#define NWIN    64
#define BW      (BATCH*NWIN)     // 2048 windows
#define MROWS   (BW*NTOK)        // 100352 tokens
#define MLPH    768

// ---------------- scratch ----------------
__device__ float g_q[BW*HEADS*NTOK*HDIM];
__device__ float g_k[BW*HEADS*NTOK*HDIM];
__device__ float g_v[BW*HEADS*NTOK*HDIM];
__device__ float g_attnout[MROWS*CH];
__device__ float g_x1[MROWS*CH];
__device__ float g_hidden[MROWS*MLPH];
__device__ float g_rpb[HEADS*NTOK*NTOK];

__device__ __forceinline__ int row_to_pix(int m){
    int b_ = m / NTOK;
    int nn = m - b_*NTOK;
    int b  = b_ >> 6;
    int w  = b_ & 63;
    int wh = w >> 3, ww = w & 7;
    int r  = nn / 7, c = nn - r*7;
    int h  = wh*7 + r + 3; if (h >= IMGHW) h -= IMGHW;
    int x  = ww*7 + c + 3; if (x >= IMGHW) x -= IMGHW;
    return ((b*IMGHW + h)*IMGHW + x)*CH;
}

// ---------------- tf32 helpers ----------------
__device__ __forceinline__ unsigned tf32r(float x){
    unsigned u; asm("cvt.rna.tf32.f32 %0, %1;" : "=r"(u) : "f"(x)); return u;
}
__device__ __forceinline__ void mma8(float* c, const unsigned* a, const unsigned* b){
    asm volatile("mma.sync.aligned.m16n8k8.row.col.f32.tf32.tf32.f32 "
        "{%0,%1,%2,%3},{%4,%5,%6,%7},{%8,%9},{%0,%1,%2,%3};"
        : "+f"(c[0]), "+f"(c[1]), "+f"(c[2]), "+f"(c[3])
        : "r"(a[0]), "r"(a[1]), "r"(a[2]), "r"(a[3]), "r"(b[0]), "r"(b[1]));
}

// ---------------- kernel 0: CPB MLP -> bias table ----------------
__global__ __launch_bounds__(256)
void cpb_kernel(const float* __restrict__ w1, const float* __restrict__ b1,
                const float* __restrict__ w2){
    __shared__ float tbl[169*HEADS];
    const int tid = threadIdx.x;
    if (tid < 169){
        int dh = tid / 13, dw = tid - 13*(tid/13);
        float th = (float)(dh - 6) / 6.0f * 7.0f;
        float tw = (float)(dw - 6) / 6.0f * 7.0f;
        float sh = (th > 0.f) ? 1.f : ((th < 0.f) ? -1.f : 0.f);
        float sw = (tw > 0.f) ? 1.f : ((tw < 0.f) ? -1.f : 0.f);
        const float inv_log2_7 = 1.0f / log2f(7.0f);
        th = sh * log2f(fabsf(th) + 1.0f) * inv_log2_7;
        tw = sw * log2f(fabsf(tw) + 1.0f) * inv_log2_7;
        float acc[HEADS];
        #pragma unroll
        for (int h = 0; h < HEADS; h++) acc[h] = 0.f;
        for (int j = 0; j < 512; j++){
            float hv = w1[j*2]*th + w1[j*2+1]*tw + b1[j];
            hv = (hv > 0.f) ? hv : 0.01f*hv;
            #pragma unroll
            for (int h = 0; h < HEADS; h++) acc[h] += w2[h*512 + j] * hv;
        }
        #pragma unroll
        for (int h = 0; h < HEADS; h++) tbl[tid*HEADS + h] = acc[h];
    }
    __syncthreads();
    for (int p = tid; p < HEADS*NTOK*NTOK; p += 256){
        int h   = p / (NTOK*NTOK);
        int rem = p - h*(NTOK*NTOK);
        int i   = rem / NTOK, j = rem - i*NTOK;
        int dh  = i/7 - j/7 + 6;
        int dw  = (i - 7*(i/7)) - (j - 7*(j/7)) + 6;
        float v = tbl[(dh*13 + dw)*HEADS + h];
        g_rpb[p] = 14.0f / (1.0f + expf(-v));
    }
}

// ---------------- kernel 1: QKV GEMM, 3xTF32 split, pipelined ----------------
// BM=128, BN=64, BK=16, KT=12. 8 warps (4x2), warp 32x32.
__global__ __launch_bounds__(256)
void qkv_kernel(const float* __restrict__ x, const float* __restrict__ w,
                const float* __restrict__ bias){
    __shared__ float As[2][128][20];
    __shared__ float Bs[2][64][20];
    __shared__ int rpix[128];
    __shared__ int rq[128];
    const int tid  = threadIdx.x;
    const int m0   = blockIdx.x * 128;
    const int n0   = blockIdx.y * 64;
    const int warp = tid >> 5, lane = tid & 31;
    const int g = lane >> 2, t = lane & 3;
    const int warp_m = warp & 3, warp_n = warp >> 2;
    const int m_w = warp_m*32, n_w = warp_n*32;
    if (tid < 128){
        int m = m0 + tid;
        rpix[tid] = row_to_pix(m);
        int b_ = m / NTOK; int nn = m - b_*NTOK;
        rq[tid] = b_*(HEADS*NTOK*HDIM) + nn*HDIM;
    }
    const int rowA = tid >> 1, ka = (tid & 1) * 8;
    const int rowB = tid >> 2, kb = (tid & 3) * 4;
    float c[2][4][4];
    #pragma unroll
    for (int i=0;i<2;i++) for (int j=0;j<4;j++) for (int q=0;q<4;q++) c[i][j][q]=0.f;
    __syncthreads();
    const float* pA = x + rpix[rowA] + ka;
    const float* pB = w + (n0 + rowB)*CH + kb;
    // prologue: tile 0
    {
        float4 a0 = *(const float4*)(pA);
        float4 a1 = *(const float4*)(pA + 4);
        float4 bv = *(const float4*)(pB);
        As[0][rowA][ka+0]=a0.x; As[0][rowA][ka+1]=a0.y; As[0][rowA][ka+2]=a0.z; As[0][rowA][ka+3]=a0.w;
        As[0][rowA][ka+4]=a1.x; As[0][rowA][ka+5]=a1.y; As[0][rowA][ka+6]=a1.z; As[0][rowA][ka+7]=a1.w;
        Bs[0][rowB][kb+0]=bv.x; Bs[0][rowB][kb+1]=bv.y; Bs[0][rowB][kb+2]=bv.z; Bs[0][rowB][kb+3]=bv.w;
    }
    __syncthreads();
    int p = 0;
    for (int kt = 0; kt < 12; kt++){
        float4 na0, na1, nbv;
        if (kt < 11){
            na0 = *(const float4*)(pA + (kt+1)*16);
            na1 = *(const float4*)(pA + (kt+1)*16 + 4);
            nbv = *(const float4*)(pB + (kt+1)*16);
        }
        #pragma unroll
        for (int ks = 0; ks < 2; ks++){
            const int k0 = ks*8;
            unsigned ah[2][4], al[2][4];
            #pragma unroll
            for (int mi = 0; mi < 2; mi++){
                int mr = m_w + mi*16;
                float f;
                f = As[p][mr+g][k0+t];     ah[mi][0]=tf32r(f); al[mi][0]=tf32r(f-__uint_as_float(ah[mi][0]));
                f = As[p][mr+8+g][k0+t];   ah[mi][1]=tf32r(f); al[mi][1]=tf32r(f-__uint_as_float(ah[mi][1]));
                f = As[p][mr+g][k0+t+4];   ah[mi][2]=tf32r(f); al[mi][2]=tf32r(f-__uint_as_float(ah[mi][2]));
                f = As[p][mr+8+g][k0+t+4]; ah[mi][3]=tf32r(f); al[mi][3]=tf32r(f-__uint_as_float(ah[mi][3]));
            }
            unsigned bh[4][2], bl[4][2];
            #pragma unroll
            for (int ni = 0; ni < 4; ni++){
                int nr = n_w + ni*8 + g;
                float f;
                f = Bs[p][nr][k0+t];   bh[ni][0]=tf32r(f); bl[ni][0]=tf32r(f-__uint_as_float(bh[ni][0]));
                f = Bs[p][nr][k0+t+4]; bh[ni][1]=tf32r(f); bl[ni][1]=tf32r(f-__uint_as_float(bh[ni][1]));
            }
            #pragma unroll
            for (int mi = 0; mi < 2; mi++)
                #pragma unroll
                for (int ni = 0; ni < 4; ni++){
                    mma8(c[mi][ni], al[mi], bh[ni]);
                    mma8(c[mi][ni], ah[mi], bl[ni]);
                    mma8(c[mi][ni], ah[mi], bh[ni]);
                }
        }
        if (kt < 11){
            int q = 1-p;
            As[q][rowA][ka+0]=na0.x; As[q][rowA][ka+1]=na0.y; As[q][rowA][ka+2]=na0.z; As[q][rowA][ka+3]=na0.w;
            As[q][rowA][ka+4]=na1.x; As[q][rowA][ka+5]=na1.y; As[q][rowA][ka+6]=na1.z; As[q][rowA][ka+7]=na1.w;
            Bs[q][rowB][kb+0]=nbv.x; Bs[q][rowB][kb+1]=nbv.y; Bs[q][rowB][kb+2]=nbv.z; Bs[q][rowB][kb+3]=nbv.w;
            __syncthreads();
        }
        p ^= 1;
    }
    #pragma unroll
    for (int mi = 0; mi < 2; mi++){
        #pragma unroll
        for (int ni = 0; ni < 4; ni++){
            int col  = n0 + n_w + ni*8 + t*2;
            int slot = col / 192;
            int rem  = col - slot*192;
            float* dst = (slot == 0) ? g_q : ((slot == 1) ? g_k : g_v);
            int off = (rem >> 5)*(NTOK*HDIM) + (rem & 31);
            float2 bv = *(const float2*)(bias + col);
            int r0 = m_w + mi*16 + g;
            float2 o0 = {c[mi][ni][0] + bv.x, c[mi][ni][1] + bv.y};
            *(float2*)(dst + rq[r0] + off) = o0;
            float2 o1 = {c[mi][ni][2] + bv.x, c[mi][ni][3] + bv.y};
            *(float2*)(dst + rq[r0+8] + off) = o1;
        }
    }
}

// ---------------- kernel 2: windowed attention ----------------
__global__ __launch_bounds__(256)
void attn_kernel(const float* __restrict__ logit_scale){
    __shared__ __align__(16) float qT[32*52];
    __shared__ __align__(16) float kT[32*52];
    __shared__ __align__(16) float vS[NTOK*HDIM];
    __shared__ float S[NTOK*NTOK];
    __shared__ __align__(16) float PT[NTOK*52];
    __shared__ int lab[NTOK];
    const int b_   = blockIdx.x;
    const int head = blockIdx.y;
    const int tid  = threadIdx.x;
    const float* qg = g_q + (b_*HEADS + head)*NTOK*HDIM;
    const float* kg = g_k + (b_*HEADS + head)*NTOK*HDIM;
    const float* vg = g_v + (b_*HEADS + head)*NTOK*HDIM;

    for (int idx = tid; idx < 32*52; idx += 256){ qT[idx]=0.f; kT[idx]=0.f; }
    for (int idx = tid; idx < NTOK*52; idx += 256){ PT[idx]=0.f; }
    __syncthreads();
    for (int idx = tid; idx < NTOK*HDIM; idx += 256){
        int n = idx >> 5, d = idx & 31;
        qT[d*52 + n] = qg[idx];
        kT[d*52 + n] = kg[idx];
        vS[idx]      = vg[idx];
    }
    if (tid < NTOK){
        int w  = b_ & 63;
        int wh = w >> 3, ww = w & 7;
        int r  = tid / 7, c = tid - 7*r;
        int hp = wh*7 + r, wp = ww*7 + c;
        int rb = (hp < 49) ? 0 : ((hp < 53) ? 1 : 2);
        int cb = (wp < 49) ? 0 : ((wp < 53) ? 1 : 2);
        lab[tid] = rb*3 + cb;
    }
    __syncthreads();
    if (tid < 2*NTOK){
        int i = (tid < NTOK) ? tid : tid - NTOK;
        float* base = (tid < NTOK) ? qT : kT;
        float ss = 0.f;
        #pragma unroll
        for (int d = 0; d < 32; d++){ float v = base[d*52 + i]; ss += v*v; }
        float inv = 1.0f / fmaxf(sqrtf(ss), 1e-12f);
        #pragma unroll
        for (int d = 0; d < 32; d++) base[d*52 + i] *= inv;
    }
    __syncthreads();
    const float sc = expf(fminf(logit_scale[head], 4.60517019f));
    if (tid < 169){
        int bi = tid / 13, bj = tid - 13*bi;
        int i0 = bi*4, j0 = bj*4;
        float acc[4][4];
        #pragma unroll
        for (int a=0;a<4;a++) for (int b=0;b<4;b++) acc[a][b]=0.f;
        #pragma unroll
        for (int d = 0; d < 32; d++){
            float4 qv = *(const float4*)&qT[d*52 + i0];
            float4 kv = *(const float4*)&kT[d*52 + j0];
            float qa[4] = {qv.x,qv.y,qv.z,qv.w};
            float kk[4] = {kv.x,kv.y,kv.z,kv.w};
            #pragma unroll
            for (int a=0;a<4;a++)
                #pragma unroll
                for (int b=0;b<4;b++) acc[a][b] += qa[a]*kk[b];
        }
        const float* rpb = g_rpb + head*NTOK*NTOK;
        #pragma unroll
        for (int a=0;a<4;a++){
            int i = i0 + a;
            if (i < NTOK){
                #pragma unroll
                for (int b=0;b<4;b++){
                    int j = j0 + b;
                    if (j < NTOK){
                        float mval = (lab[i] == lab[j]) ? 0.f : -100.f;
                        S[i*NTOK + j] = acc[a][b]*sc + rpb[i*NTOK + j] + mval;
                    }
                }
            }
        }
    }
    __syncthreads();
    if (tid < NTOK){
        int i = tid;
        float mx = -1e30f;
        for (int j = 0; j < NTOK; j++) mx = fmaxf(mx, S[i*NTOK + j]);
        float sum = 0.f;
        for (int j = 0; j < NTOK; j++){
            float e = expf(S[i*NTOK + j] - mx);
            PT[j*52 + i] = e;
            sum += e;
        }
        float inv = 1.0f / sum;
        for (int j = 0; j < NTOK; j++) PT[j*52 + i] *= inv;
    }
    __syncthreads();
    if (tid < 104){
        int bi = tid >> 3, bd = tid & 7;
        int i0 = bi*4, d0 = bd*4;
        float acc[4][4];
        #pragma unroll
        for (int a=0;a<4;a++) for (int b=0;b<4;b++) acc[a][b]=0.f;
        for (int j = 0; j < NTOK; j++){
            float4 pv = *(const float4*)&PT[j*52 + i0];
            float4 vv = *(const float4*)&vS[j*HDIM + d0];
            float pa[4] = {pv.x,pv.y,pv.z,pv.w};
            float va[4] = {vv.x,vv.y,vv.z,vv.w};
            #pragma unroll
            for (int a=0;a<4;a++)
                #pragma unroll
                for (int b=0;b<4;b++) acc[a][b] += pa[a]*va[b];
        }
        float* outb = g_attnout + (b_*NTOK)*CH + head*HDIM;
        #pragma unroll
        for (int a=0;a<4;a++){
            int i = i0 + a;
            if (i < NTOK){
                float4 o = {acc[a][0], acc[a][1], acc[a][2], acc[a][3]};
                *(float4*)(outb + i*CH + d0) = o;
            }
        }
    }
}

// ---------------- kernels 3/5: GEMM(BMx192) + LN + residual, pipelined ----------------
// BM=64, BN=192, BK=16. 8 warps (2x4), warp 32x48.
template<bool PIX>
__global__ __launch_bounds__(256)
void gemm_ln_kernel(const float* __restrict__ A, const float* __restrict__ w,
                    const float* __restrict__ bias, const float* __restrict__ nw,
                    const float* __restrict__ nb, const float* __restrict__ res,
                    float* __restrict__ out, int K){
    __shared__ float As[2][64][20];
    __shared__ float Bs[2][192][20];
    __shared__ float red_s[64][4], red_q[64][4];
    __shared__ int rpix[64];
    const int tid  = threadIdx.x;
    const int m0   = blockIdx.x * 64;
    const int warp = tid >> 5, lane = tid & 31;
    const int g = lane >> 2, t = lane & 3;
    const int warp_m = warp >> 2, warp_n = warp & 3;
    const int m_w = warp_m*32, n_w = warp_n*48;
    if (PIX && tid < 64) rpix[tid] = row_to_pix(m0 + tid);
    const int rowA = tid >> 2, ka = (tid & 3) * 4;
    float c[2][6][4];
    #pragma unroll
    for (int i=0;i<2;i++) for (int j=0;j<6;j++) for (int q=0;q<4;q++) c[i][j][q]=0.f;

    const float* pA  = A + (long)(m0 + rowA)*K + ka;
    const float* pB0 = w + (long)(rowA      )*K + ka;
    const float* pB1 = w + (long)(rowA + 64 )*K + ka;
    const float* pB2 = w + (long)(rowA + 128)*K + ka;
    {
        float4 av  = *(const float4*)(pA);
        float4 bv0 = *(const float4*)(pB0);
        float4 bv1 = *(const float4*)(pB1);
        float4 bv2 = *(const float4*)(pB2);
        As[0][rowA][ka+0]=av.x; As[0][rowA][ka+1]=av.y; As[0][rowA][ka+2]=av.z; As[0][rowA][ka+3]=av.w;
        Bs[0][rowA][ka+0]=bv0.x; Bs[0][rowA][ka+1]=bv0.y; Bs[0][rowA][ka+2]=bv0.z; Bs[0][rowA][ka+3]=bv0.w;
        Bs[0][rowA+64][ka+0]=bv1.x; Bs[0][rowA+64][ka+1]=bv1.y; Bs[0][rowA+64][ka+2]=bv1.z; Bs[0][rowA+64][ka+3]=bv1.w;
        Bs[0][rowA+128][ka+0]=bv2.x; Bs[0][rowA+128][ka+1]=bv2.y; Bs[0][rowA+128][ka+2]=bv2.z; Bs[0][rowA+128][ka+3]=bv2.w;
    }
    __syncthreads();
    const int KT = K >> 4;
    int p = 0;
    for (int kt = 0; kt < KT; kt++){
        float4 nav, nb0, nb1, nb2;
        if (kt < KT-1){
            nav = *(const float4*)(pA  + (kt+1)*16);
            nb0 = *(const float4*)(pB0 + (kt+1)*16);
            nb1 = *(const float4*)(pB1 + (kt+1)*16);
            nb2 = *(const float4*)(pB2 + (kt+1)*16);
        }
        #pragma unroll
        for (int ks = 0; ks < 2; ks++){
            const int k0 = ks*8;
            unsigned a[2][4];
            #pragma unroll
            for (int mi = 0; mi < 2; mi++){
                int mr = m_w + mi*16;
                a[mi][0] = tf32r(As[p][mr+g][k0+t]);
                a[mi][1] = tf32r(As[p][mr+8+g][k0+t]);
                a[mi][2] = tf32r(As[p][mr+g][k0+t+4]);
                a[mi][3] = tf32r(As[p][mr+8+g][k0+t+4]);
            }
            unsigned b[6][2];
            #pragma unroll
            for (int ni = 0; ni < 6; ni++){
                int nr = n_w + ni*8 + g;
                b[ni][0] = tf32r(Bs[p][nr][k0+t]);
                b[ni][1] = tf32r(Bs[p][nr][k0+t+4]);
            }
            #pragma unroll
            for (int mi = 0; mi < 2; mi++)
                #pragma unroll
                for (int ni = 0; ni < 6; ni++)
                    mma8(c[mi][ni], a[mi], b[ni]);
        }
        if (kt < KT-1){
            int q = 1-p;
            As[q][rowA][ka+0]=nav.x; As[q][rowA][ka+1]=nav.y; As[q][rowA][ka+2]=nav.z; As[q][rowA][ka+3]=nav.w;
            Bs[q][rowA][ka+0]=nb0.x; Bs[q][rowA][ka+1]=nb0.y; Bs[q][rowA][ka+2]=nb0.z; Bs[q][rowA][ka+3]=nb0.w;
            Bs[q][rowA+64][ka+0]=nb1.x; Bs[q][rowA+64][ka+1]=nb1.y; Bs[q][rowA+64][ka+2]=nb1.z; Bs[q][rowA+64][ka+3]=nb1.w;
            Bs[q][rowA+128][ka+0]=nb2.x; Bs[q][rowA+128][ka+1]=nb2.y; Bs[q][rowA+128][ka+2]=nb2.z; Bs[q][rowA+128][ka+3]=nb2.w;
            __syncthreads();
        }
        p ^= 1;
    }
    float2 bb[6];
    #pragma unroll
    for (int ni = 0; ni < 6; ni++){
        int col = n_w + ni*8 + t*2;
        bb[ni] = *(const float2*)(bias + col);
        #pragma unroll
        for (int mi = 0; mi < 2; mi++){
            c[mi][ni][0] += bb[ni].x; c[mi][ni][1] += bb[ni].y;
            c[mi][ni][2] += bb[ni].x; c[mi][ni][3] += bb[ni].y;
        }
    }
    #pragma unroll
    for (int mi = 0; mi < 2; mi++){
        float s0=0,q0=0,s1=0,q1=0;
        #pragma unroll
        for (int ni = 0; ni < 6; ni++){
            s0 += c[mi][ni][0] + c[mi][ni][1];
            q0 += c[mi][ni][0]*c[mi][ni][0] + c[mi][ni][1]*c[mi][ni][1];
            s1 += c[mi][ni][2] + c[mi][ni][3];
            q1 += c[mi][ni][2]*c[mi][ni][2] + c[mi][ni][3]*c[mi][ni][3];
        }
        #pragma unroll
        for (int off = 1; off <= 2; off <<= 1){
            s0 += __shfl_xor_sync(0xffffffffu, s0, off);
            q0 += __shfl_xor_sync(0xffffffffu, q0, off);
            s1 += __shfl_xor_sync(0xffffffffu, s1, off);
            q1 += __shfl_xor_sync(0xffffffffu, q1, off);
        }
        if (t == 0){
            int r0 = m_w + mi*16 + g;
            red_s[r0][warp_n] = s0; red_q[r0][warp_n] = q0;
            red_s[r0+8][warp_n] = s1; red_q[r0+8][warp_n] = q1;
        }
    }
    __syncthreads();
    const float invC = 1.0f / 192.0f;
    #pragma unroll
    for (int mi = 0; mi < 2; mi++){
        #pragma unroll
        for (int half = 0; half < 2; half++){
            int row = m_w + mi*16 + half*8 + g;
            float s = red_s[row][0] + red_s[row][1] + red_s[row][2] + red_s[row][3];
            float q = red_q[row][0] + red_q[row][1] + red_q[row][2] + red_q[row][3];
            float mean = s * invC;
            float var  = q * invC - mean*mean;
            float rstd = rsqrtf(var + 1e-5f);
            long gi = PIX ? (long)rpix[row] : (long)(m0 + row)*CH;
            #pragma unroll
            for (int ni = 0; ni < 6; ni++){
                int col = n_w + ni*8 + t*2;
                float y0 = c[mi][ni][half*2+0];
                float y1 = c[mi][ni][half*2+1];
                float2 rv = *(const float2*)(res + gi + col);
                float2 wv = *(const float2*)(nw + col);
                float2 bn = *(const float2*)(nb + col);
                float2 o;
                o.x = rv.x + (y0 - mean)*rstd*wv.x + bn.x;
                o.y = rv.y + (y1 - mean)*rstd*wv.y + bn.y;
                *(float2*)(out + gi + col) = o;
            }
        }
    }
}

// ---------------- kernel 4: fc1 GEMM + exact GELU, pipelined ----------------
// BM=128, BN=64, BK=16, KT=12.
__global__ __launch_bounds__(256)
void fc1_kernel(const float* __restrict__ w, const float* __restrict__ bias){
    __shared__ float As[2][128][20];
    __shared__ float Bs[2][64][20];
    const int tid  = threadIdx.x;
    const int m0   = blockIdx.x * 128;
    const int n0   = blockIdx.y * 64;
    const int warp = tid >> 5, lane = tid & 31;
    const int g = lane >> 2, t = lane & 3;
    const int warp_m = warp & 3, warp_n = warp >> 2;
    const int m_w = warp_m*32, n_w = warp_n*32;
    const int rowA = tid >> 1, ka = (tid & 1) * 8;
    const int rowB = tid >> 2, kb = (tid & 3) * 4;
    float c[2][4][4];
    #pragma unroll
    for (int i=0;i<2;i++) for (int j=0;j<4;j++) for (int q=0;q<4;q++) c[i][j][q]=0.f;

    const float* pA = g_x1 + (long)(m0 + rowA)*CH + ka;
    const float* pB = w + (long)(n0 + rowB)*CH + kb;
    {
        float4 a0 = *(const float4*)(pA);
        float4 a1 = *(const float4*)(pA + 4);
        float4 bv = *(const float4*)(pB);
        As[0][rowA][ka+0]=a0.x; As[0][rowA][ka+1]=a0.y; As[0][rowA][ka+2]=a0.z; As[0][rowA][ka+3]=a0.w;
        As[0][rowA][ka+4]=a1.x; As[0][rowA][ka+5]=a1.y; As[0][rowA][ka+6]=a1.z; As[0][rowA][ka+7]=a1.w;
        Bs[0][rowB][kb+0]=bv.x; Bs[0][rowB][kb+1]=bv.y; Bs[0][rowB][kb+2]=bv.z; Bs[0][rowB][kb+3]=bv.w;
    }
    __syncthreads();
    int p = 0;
    for (int kt = 0; kt < 12; kt++){
        float4 na0, na1, nbv;
        if (kt < 11){
            na0 = *(const float4*)(pA + (kt+1)*16);
            na1 = *(const float4*)(pA + (kt+1)*16 + 4);
            nbv = *(const float4*)(pB + (kt+1)*16);
        }
        #pragma unroll
        for (int ks = 0; ks < 2; ks++){
            const int k0 = ks*8;
            unsigned a[2][4];
            #pragma unroll
            for (int mi = 0; mi < 2; mi++){
                int mr = m_w + mi*16;
                a[mi][0] = tf32r(As[p][mr+g][k0+t]);
                a[mi][1] = tf32r(As[p][mr+8+g][k0+t]);
                a[mi][2] = tf32r(As[p][mr+g][k0+t+4]);
                a[mi][3] = tf32r(As[p][mr+8+g][k0+t+4]);
            }
            unsigned b[4][2];
            #pragma unroll
            for (int ni = 0; ni < 4; ni++){
                int nr = n_w + ni*8 + g;
                b[ni][0] = tf32r(Bs[p][nr][k0+t]);
                b[ni][1] = tf32r(Bs[p][nr][k0+t+4]);
            }
            #pragma unroll
            for (int mi = 0; mi < 2; mi++)
                #pragma unroll
                for (int ni = 0; ni < 4; ni++)
                    mma8(c[mi][ni], a[mi], b[ni]);
        }
        if (kt < 11){
            int q = 1-p;
            As[q][rowA][ka+0]=na0.x; As[q][rowA][ka+1]=na0.y; As[q][rowA][ka+2]=na0.z; As[q][rowA][ka+3]=na0.w;
            As[q][rowA][ka+4]=na1.x; As[q][rowA][ka+5]=na1.y; As[q][rowA][ka+6]=na1.z; As[q][rowA][ka+7]=na1.w;
            Bs[q][rowB][kb+0]=nbv.x; Bs[q][rowB][kb+1]=nbv.y; Bs[q][rowB][kb+2]=nbv.z; Bs[q][rowB][kb+3]=nbv.w;
            __syncthreads();
        }
        p ^= 1;
    }
    #pragma unroll
    for (int mi = 0; mi < 2; mi++){
        #pragma unroll
        for (int ni = 0; ni < 4; ni++){
            int col = n0 + n_w + ni*8 + t*2;
            float2 bv = *(const float2*)(bias + col);
            int r0 = m0 + m_w + mi*16 + g;
            float v0 = c[mi][ni][0] + bv.x;
            float v1 = c[mi][ni][1] + bv.y;
            float v2 = c[mi][ni][2] + bv.x;
            float v3 = c[mi][ni][3] + bv.y;
            float2 o0, o1;
            o0.x = v0 * 0.5f * (1.0f + erff(v0 * 0.70710678118654752f));
            o0.y = v1 * 0.5f * (1.0f + erff(v1 * 0.70710678118654752f));
            o1.x = v2 * 0.5f * (1.0f + erff(v2 * 0.70710678118654752f));
            o1.y = v3 * 0.5f * (1.0f + erff(v3 * 0.70710678118654752f));
            *(float2*)(g_hidden + (long)r0*MLPH + col) = o0;
            *(float2*)(g_hidden + (long)(r0+8)*MLPH + col) = o1;
        }
    }
}

// ---------------- launch ----------------
extern "C" void kernel_launch(void* const* d_in, const int* in_sizes, int n_in,
                              void* d_out, int out_size){
    const float* x        = (const float*)d_in[0];
    const float* qkv_w    = (const float*)d_in[1];
    const float* qkv_b    = (const float*)d_in[2];
    const float* proj_w   = (const float*)d_in[3];
    const float* proj_b   = (const float*)d_in[4];
    const float* lscale   = (const float*)d_in[5];
    const float* cpb_w1   = (const float*)d_in[6];
    const float* cpb_b1   = (const float*)d_in[7];
    const float* cpb_w2   = (const float*)d_in[8];
    const float* norm1_w  = (const float*)d_in[9];
    const float* norm1_b  = (const float*)d_in[10];
    const float* norm2_w  = (const float*)d_in[11];
    const float* norm2_b  = (const float*)d_in[12];
    const float* fc1_w    = (const float*)d_in[13];
    const float* fc1_b    = (const float*)d_in[14];
    const float* fc2_w    = (const float*)d_in[15];
    const float* fc2_b    = (const float*)d_in[16];
    float* out = (float*)d_out;

    float *p_attnout, *p_x1, *p_hidden;
    cudaGetSymbolAddress((void**)&p_attnout, g_attnout);
    cudaGetSymbolAddress((void**)&p_x1, g_x1);
    cudaGetSymbolAddress((void**)&p_hidden, g_hidden);

    cpb_kernel<<<1, 256>>>(cpb_w1, cpb_b1, cpb_w2);
    qkv_kernel<<<dim3(MROWS/128, 576/64), 256>>>(x, qkv_w, qkv_b);
    attn_kernel<<<dim3(BW, HEADS), 256>>>(lscale);
    gemm_ln_kernel<true><<<MROWS/64, 256>>>(p_attnout, proj_w, proj_b,
                                            norm1_w, norm1_b, x, p_x1, CH);
    fc1_kernel<<<dim3(MROWS/128, MLPH/64), 256>>>(fc1_w, fc1_b);
    gemm_ln_kernel<false><<<MROWS/64, 256>>>(p_hidden, fc2_w, fc2_b,
                                             norm2_w, norm2_b, p_x1, out, MLPH);
}